// round 8
// baseline (speedup 1.0000x reference)
#include <cuda_runtime.h>
#include <cuda_fp16.h>
#include <cstdint>

// Fused causal self-attention head, mma.sync m16n8k16 fp16 (fp32 accum) + ldmatrix.
// Register softmax (no fp32 S roundtrip) + causal work skipping.
// B=1024, T=128, C=384, HS=64, fp32 in/out.
// One CTA per batch, 512 threads (16 warps), ~105KB dynamic smem.

static constexpr int kT   = 128;
static constexpr int kC   = 384;
static constexpr int kHS  = 64;
static constexpr int kCH  = 32;             // K-chunk (floats)
static constexpr int kNCH = kC / kCH;       // 12
static constexpr int kNW  = 192;            // combined N = 3*64 (Wk|Wq|Wv)

// strides in 4B words (half2 units for fp16 regions)
static constexpr int LDXW = 20;             // x/w staging rows: 16 half2 data + 4 pad
static constexpr int LDH  = 36;             // K/Q rows: 32 half2 + 4 pad
static constexpr int LDVT = 68;             // Vt rows: 64 half2 + 4 pad
static constexpr int LDP  = 68;             // P rows: 64 half2 + 4 pad

static constexpr int W_K  = 0;
static constexpr int W_Q  = W_K + kT * LDH;         // 4608
static constexpr int W_VT = W_Q + kT * LDH;         // 9216
static constexpr int W_U  = W_VT + kHS * LDVT;      // 13568 (union region)
static constexpr int XBUF_W = kT  * LDXW;           // 2560
static constexpr int WBUF_W = kNW * LDXW;           // 3840
static constexpr int BUF_W  = XBUF_W + WBUF_W;      // 6400 (2 bufs alias P/stats)
static constexpr int W_P  = W_U;                    // P half2 [128][68]
static constexpr int W_ST = W_U + kT * LDP;         // stats float2 [128][4]
static constexpr int SMEM_WORDS = W_U + 2 * BUF_W;  // 26368
static constexpr int SMEM_BYTES = SMEM_WORDS * 4;   // 105472

// ---------------- helpers ----------------
__device__ __forceinline__ uint32_t pkh2(float a, float b) {
    __half2 h = __floats2half2_rn(a, b);
    return *(uint32_t*)&h;
}
__device__ __forceinline__ uint32_t s2u(const void* p) {
    uint32_t a;
    asm("{ .reg .u64 t; cvta.to.shared.u64 t, %1; cvt.u32.u64 %0, t; }" : "=r"(a) : "l"(p));
    return a;
}
__device__ __forceinline__ void mma_f16(float c[4], const uint32_t a[4],
                                        uint32_t b0, uint32_t b1) {
    asm volatile(
        "mma.sync.aligned.m16n8k16.row.col.f32.f16.f16.f32 "
        "{%0,%1,%2,%3}, {%4,%5,%6,%7}, {%8,%9}, {%0,%1,%2,%3};"
        : "+f"(c[0]), "+f"(c[1]), "+f"(c[2]), "+f"(c[3])
        : "r"(a[0]), "r"(a[1]), "r"(a[2]), "r"(a[3]), "r"(b0), "r"(b1));
}
__device__ __forceinline__ void ldmx4(uint32_t& r0, uint32_t& r1,
                                      uint32_t& r2, uint32_t& r3, uint32_t addr) {
    asm volatile("ldmatrix.sync.aligned.m8n8.x4.shared.b16 {%0,%1,%2,%3}, [%4];"
                 : "=r"(r0), "=r"(r1), "=r"(r2), "=r"(r3) : "r"(addr));
}

// ---------------- kernel ----------------
__global__ void __launch_bounds__(512, 1)
attn_mma_kernel(const float* __restrict__ x,
                const float* __restrict__ Wk,
                const float* __restrict__ Wq,
                const float* __restrict__ Wv,
                float* __restrict__ out) {
    extern __shared__ uint32_t sm[];
    const uint32_t smu = s2u(sm);
    const int tid  = threadIdx.x;
    const int wid  = tid >> 5;
    const int lane = tid & 31;
    const int g4   = lane >> 2;      // 0..7
    const int t4   = lane & 3;       // 0..3
    const int wm   = wid & 3;        // m-group
    const int wn   = wid >> 2;       // n-group
    const int l15  = lane & 15;      // ldmatrix row select
    const int l16w = (lane >> 4) * 4; // ldmatrix col-half select (words)
    const int b    = blockIdx.x;
    const float* xb = x + (size_t)b * (kT * kC);

    // ===== Stage A: KQV = x @ [Wk|Wq|Wv]^T, K-chunked, reg-prefetch dbuf =====
    float4 xr[2], wr[3];
    {
#pragma unroll
        for (int r = 0; r < 2; ++r) {
            int idx = tid + 512 * r, t = idx >> 3, f4 = idx & 7;
            xr[r] = *(const float4*)(xb + t * kC + f4 * 4);
        }
#pragma unroll
        for (int r = 0; r < 3; ++r) {
            int idx = tid + 512 * r, n = idx >> 3, f4 = idx & 7;
            const float* Wm = (n < 64) ? (Wk + n * kC)
                              : (n < 128) ? (Wq + (n - 64) * kC)
                                          : (Wv + (n - 128) * kC);
            wr[r] = *(const float4*)(Wm + f4 * 4);
        }
    }
    {
        uint32_t* bx = sm + W_U;
        uint32_t* bw = bx + XBUF_W;
#pragma unroll
        for (int r = 0; r < 2; ++r) {
            int idx = tid + 512 * r, t = idx >> 3, f4 = idx & 7;
            *(uint2*)(bx + t * LDXW + f4 * 2) =
                make_uint2(pkh2(xr[r].x, xr[r].y), pkh2(xr[r].z, xr[r].w));
        }
#pragma unroll
        for (int r = 0; r < 3; ++r) {
            int idx = tid + 512 * r, n = idx >> 3, f4 = idx & 7;
            *(uint2*)(bw + n * LDXW + f4 * 2) =
                make_uint2(pkh2(wr[r].x, wr[r].y), pkh2(wr[r].z, wr[r].w));
        }
    }
    __syncthreads();

    float c[2][6][4];
#pragma unroll
    for (int mt = 0; mt < 2; ++mt)
#pragma unroll
        for (int nt = 0; nt < 6; ++nt)
#pragma unroll
            for (int j = 0; j < 4; ++j) c[mt][nt][j] = 0.f;

    for (int cb = 0; cb < kNCH; ++cb) {
        const int p = cb & 1;
        if (cb + 1 < kNCH) {
            const int cbase = (cb + 1) * kCH;
#pragma unroll
            for (int r = 0; r < 2; ++r) {
                int idx = tid + 512 * r, t = idx >> 3, f4 = idx & 7;
                xr[r] = *(const float4*)(xb + t * kC + cbase + f4 * 4);
            }
#pragma unroll
            for (int r = 0; r < 3; ++r) {
                int idx = tid + 512 * r, n = idx >> 3, f4 = idx & 7;
                const float* Wm = (n < 64) ? (Wk + n * kC)
                                  : (n < 128) ? (Wq + (n - 64) * kC)
                                              : (Wv + (n - 128) * kC);
                wr[r] = *(const float4*)(Wm + cbase + f4 * 4);
            }
        }
        {
            const uint32_t bx = smu + 4 * (uint32_t)(W_U + p * BUF_W);
            const uint32_t bw = bx + 4 * (uint32_t)XBUF_W;
#pragma unroll
            for (int kk = 0; kk < 2; ++kk) {
                uint32_t a[2][4];
#pragma unroll
                for (int mt = 0; mt < 2; ++mt)
                    ldmx4(a[mt][0], a[mt][1], a[mt][2], a[mt][3],
                          bx + 4 * ((wm * 32 + mt * 16 + l15) * LDXW + kk * 8 + l16w));
#pragma unroll
                for (int np = 0; np < 3; ++np) {
                    uint32_t r0, r1, r2, r3;
                    ldmx4(r0, r1, r2, r3,
                          bw + 4 * ((wn * 48 + np * 16 + l15) * LDXW + kk * 8 + l16w));
                    mma_f16(c[0][2 * np    ], a[0], r0, r2);
                    mma_f16(c[1][2 * np    ], a[1], r0, r2);
                    mma_f16(c[0][2 * np + 1], a[0], r1, r3);
                    mma_f16(c[1][2 * np + 1], a[1], r1, r3);
                }
            }
        }
        if (cb + 1 < kNCH) {
            uint32_t* bx = sm + W_U + (p ^ 1) * BUF_W;
            uint32_t* bw = bx + XBUF_W;
#pragma unroll
            for (int r = 0; r < 2; ++r) {
                int idx = tid + 512 * r, t = idx >> 3, f4 = idx & 7;
                *(uint2*)(bx + t * LDXW + f4 * 2) =
                    make_uint2(pkh2(xr[r].x, xr[r].y), pkh2(xr[r].z, xr[r].w));
            }
#pragma unroll
            for (int r = 0; r < 3; ++r) {
                int idx = tid + 512 * r, n = idx >> 3, f4 = idx & 7;
                *(uint2*)(bw + n * LDXW + f4 * 2) =
                    make_uint2(pkh2(wr[r].x, wr[r].y), pkh2(wr[r].z, wr[r].w));
            }
        }
        __syncthreads();
    }

    // epilogue: K,Q row-major half2 [t][h]; V transposed half [h][s]
    {
        __half* vh = (__half*)(sm + W_VT);
#pragma unroll
        for (int mt = 0; mt < 2; ++mt) {
            int r0 = wm * 32 + mt * 16 + g4, r1 = r0 + 8;
#pragma unroll
            for (int nt = 0; nt < 6; ++nt) {
                int gc = wn * 48 + nt * 8 + 2 * t4;
                int m = gc >> 6, col = gc & 63;
                if (m < 2) {
                    uint32_t* dst = sm + (m == 0 ? W_K : W_Q);
                    dst[r0 * LDH + (col >> 1)] = pkh2(c[mt][nt][0], c[mt][nt][1]);
                    dst[r1 * LDH + (col >> 1)] = pkh2(c[mt][nt][2], c[mt][nt][3]);
                } else {
                    vh[(col    ) * (LDVT * 2) + r0] = __float2half_rn(c[mt][nt][0]);
                    vh[(col + 1) * (LDVT * 2) + r0] = __float2half_rn(c[mt][nt][1]);
                    vh[(col    ) * (LDVT * 2) + r1] = __float2half_rn(c[mt][nt][2]);
                    vh[(col + 1) * (LDVT * 2) + r1] = __float2half_rn(c[mt][nt][3]);
                }
            }
        }
    }
    __syncthreads();

    // ===== Stage B: S = scale * Q @ K^T, register softmax =====
    // warp (wm,wn): rows wm*32..+31, cols wn*32..+31; fully masked iff wn > wm
    const bool active = (wn <= wm);
    float cs[2][4][4];
#pragma unroll
    for (int mt = 0; mt < 2; ++mt)
#pragma unroll
        for (int nt = 0; nt < 4; ++nt)
#pragma unroll
            for (int j = 0; j < 4; ++j) cs[mt][nt][j] = 0.f;

    if (active) {
#pragma unroll
        for (int kk = 0; kk < 4; ++kk) {
            uint32_t a[2][4];
#pragma unroll
            for (int mt = 0; mt < 2; ++mt)
                ldmx4(a[mt][0], a[mt][1], a[mt][2], a[mt][3],
                      smu + 4 * (W_Q + (wm * 32 + mt * 16 + l15) * LDH + kk * 8 + l16w));
#pragma unroll
            for (int np = 0; np < 2; ++np) {
                uint32_t r0, r1, r2, r3;
                ldmx4(r0, r1, r2, r3,
                      smu + 4 * (W_K + (wn * 32 + np * 16 + l15) * LDH + kk * 8 + l16w));
                mma_f16(cs[0][2 * np    ], a[0], r0, r2);
                mma_f16(cs[1][2 * np    ], a[1], r0, r2);
                mma_f16(cs[0][2 * np + 1], a[0], r1, r3);
                mma_f16(cs[1][2 * np + 1], a[1], r1, r3);
            }
        }
        // mask + scale + per-chunk (max, sumexp) via quad shuffles
        const float scale = 0.05103103630798288f;    // 384^-0.5
#pragma unroll
        for (int mt = 0; mt < 2; ++mt)
#pragma unroll
            for (int h = 0; h < 2; ++h) {
                const int row = wm * 32 + mt * 16 + g4 + h * 8;
                float m = -1e30f;
#pragma unroll
                for (int nt = 0; nt < 4; ++nt)
#pragma unroll
                    for (int j = 0; j < 2; ++j) {
                        int col = wn * 32 + nt * 8 + 2 * t4 + j;
                        float f = cs[mt][nt][2 * h + j] * scale;
                        if (col > row) f = -1e30f;
                        cs[mt][nt][2 * h + j] = f;
                        m = fmaxf(m, f);
                    }
                m = fmaxf(m, __shfl_xor_sync(0xffffffffu, m, 1));
                m = fmaxf(m, __shfl_xor_sync(0xffffffffu, m, 2));
                float s = 0.f;
#pragma unroll
                for (int nt = 0; nt < 4; ++nt)
#pragma unroll
                    for (int j = 0; j < 2; ++j)
                        s += __expf(cs[mt][nt][2 * h + j] - m);
                s += __shfl_xor_sync(0xffffffffu, s, 1);
                s += __shfl_xor_sync(0xffffffffu, s, 2);
                if (t4 == 0)
                    *(float2*)(sm + W_ST + (row * 4 + wn) * 2) = make_float2(m, s);
            }
    }
    __syncthreads();

    // combine stats, write P (half2); inactive warps zero-fill their block
    {
        const float2* st = (const float2*)(sm + W_ST);
#pragma unroll
        for (int mt = 0; mt < 2; ++mt)
#pragma unroll
            for (int h = 0; h < 2; ++h) {
                const int row = wm * 32 + mt * 16 + g4 + h * 8;
                uint32_t* rowp = sm + W_P + row * LDP;
                if (active) {
                    float m = -1e30f;
                    for (int w2 = 0; w2 <= wm; ++w2)
                        m = fmaxf(m, st[row * 4 + w2].x);
                    float s = 0.f;
                    for (int w2 = 0; w2 <= wm; ++w2) {
                        float2 v = st[row * 4 + w2];
                        s += v.y * __expf(v.x - m);
                    }
                    const float inv = 1.0f / s;
#pragma unroll
                    for (int nt = 0; nt < 4; ++nt) {
                        float e0 = __expf(cs[mt][nt][2 * h + 0] - m) * inv;
                        float e1 = __expf(cs[mt][nt][2 * h + 1] - m) * inv;
                        rowp[wn * 16 + nt * 4 + t4] = pkh2(e0, e1);
                    }
                } else {
#pragma unroll
                    for (int nt = 0; nt < 4; ++nt)
                        rowp[wn * 16 + nt * 4 + t4] = 0u;
                }
            }
    }
    __syncthreads();

    // ===== Stage D: out = P @ V, balanced causal row pairing =====
    // warp wm owns row-tiles ta=wm (kk<=wm) and tb=7-wm (kk<=7-wm): 9 kk-tiles each
    {
        const int ta = wm, tb = 7 - wm;
        float ca[2][4], cb2[2][4];
#pragma unroll
        for (int nt = 0; nt < 2; ++nt)
#pragma unroll
            for (int j = 0; j < 4; ++j) { ca[nt][j] = 0.f; cb2[nt][j] = 0.f; }
#pragma unroll
        for (int kk = 0; kk < 8; ++kk) {
            if (kk <= tb) {
                uint32_t r0, r1, r2, r3;
                ldmx4(r0, r1, r2, r3,
                      smu + 4 * (W_VT + (wn * 16 + l15) * LDVT + kk * 8 + l16w));
                uint32_t ab[4];
                ldmx4(ab[0], ab[1], ab[2], ab[3],
                      smu + 4 * (W_P + (tb * 16 + l15) * LDP + kk * 8 + l16w));
                mma_f16(cb2[0], ab, r0, r2);
                mma_f16(cb2[1], ab, r1, r3);
                if (kk <= ta) {
                    uint32_t aa[4];
                    ldmx4(aa[0], aa[1], aa[2], aa[3],
                          smu + 4 * (W_P + (ta * 16 + l15) * LDP + kk * 8 + l16w));
                    mma_f16(ca[0], aa, r0, r2);
                    mma_f16(ca[1], aa, r1, r3);
                }
            }
        }
        float* ob = out + (size_t)b * (kT * kHS);
        const int ra0 = ta * 16 + g4, ra1 = ra0 + 8;
        const int rb0 = tb * 16 + g4, rb1 = rb0 + 8;
#pragma unroll
        for (int nt = 0; nt < 2; ++nt) {
            int h0 = wn * 16 + nt * 8 + 2 * t4;
            *(float2*)(ob + ra0 * kHS + h0) = make_float2(ca[nt][0], ca[nt][1]);
            *(float2*)(ob + ra1 * kHS + h0) = make_float2(ca[nt][2], ca[nt][3]);
            *(float2*)(ob + rb0 * kHS + h0) = make_float2(cb2[nt][0], cb2[nt][1]);
            *(float2*)(ob + rb1 * kHS + h0) = make_float2(cb2[nt][2], cb2[nt][3]);
        }
    }
}

extern "C" void kernel_launch(void* const* d_in, const int* in_sizes, int n_in,
                              void* d_out, int out_size) {
    const float* x  = (const float*)d_in[0];
    const float* Wk = (const float*)d_in[1];
    const float* Wq = (const float*)d_in[2];
    const float* Wv = (const float*)d_in[3];
    float* out = (float*)d_out;

    const int B = in_sizes[0] / (kT * kC);   // 1024
    cudaFuncSetAttribute(attn_mma_kernel,
                         cudaFuncAttributeMaxDynamicSharedMemorySize, SMEM_BYTES);
    attn_mma_kernel<<<B, 512, SMEM_BYTES>>>(x, Wk, Wq, Wv, out);
}

// round 10
// speedup vs baseline: 1.0158x; 1.0158x over previous
#include <cuda_runtime.h>
#include <cuda_fp16.h>
#include <cstdint>

// Fused causal self-attention head as TWO kernels:
//  1) proj_kernel: KQV projection GEMM (fp16 mma, occ 2), writes fp16 scratch
//  2) attn_kernel: flash-style attention per batch (warp-local softmax)
// B=1024, T=128, C=384, HS=64, fp32 in/out.

static constexpr int kT  = 128;
static constexpr int kC  = 384;
static constexpr int kHS = 64;
static constexpr int kCH = 32;              // K-chunk (floats)
static constexpr int kNCH = kC / kCH;       // 12

// fp16 scratch: K,Q [b][t][h]; Vt [b][h][t]
__device__ __half g_K [1024 * 128 * 64];
__device__ __half g_Q [1024 * 128 * 64];
__device__ __half g_Vt[1024 * 64 * 128];

// ---- proj_kernel smem (words) ----
static constexpr int LDXW   = 20;                    // 16 half2 data + 4 pad
static constexpr int XBUF_W = 64  * LDXW;            // 1280
static constexpr int WBUF_W = 192 * LDXW;            // 3840
static constexpr int BUF_W  = XBUF_W + WBUF_W;       // 5120
static constexpr int SMEM1_BYTES = 2 * BUF_W * 4;    // 40960

// ---- attn_kernel smem (words) ----
static constexpr int LDH  = 36;                      // Q/K rows: 32 half2 + 4 pad
static constexpr int LDVT = 68;                      // Vt rows: 64 half2 + 4 pad
static constexpr int W2_Q  = 0;
static constexpr int W2_K  = W2_Q + kT * LDH;        // 4608
static constexpr int W2_VT = W2_K + kT * LDH;        // 9216
static constexpr int SMEM2_BYTES = (W2_VT + kHS * LDVT) * 4;   // 54272

// ---------------- helpers ----------------
__device__ __forceinline__ uint32_t pkh2(float a, float b) {
    __half2 h = __floats2half2_rn(a, b);
    return *(uint32_t*)&h;
}
__device__ __forceinline__ uint32_t s2u(const void* p) {
    uint32_t a;
    asm("{ .reg .u64 t; cvta.to.shared.u64 t, %1; cvt.u32.u64 %0, t; }" : "=r"(a) : "l"(p));
    return a;
}
__device__ __forceinline__ void mma_f16(float c[4], const uint32_t a[4],
                                        uint32_t b0, uint32_t b1) {
    asm volatile(
        "mma.sync.aligned.m16n8k16.row.col.f32.f16.f16.f32 "
        "{%0,%1,%2,%3}, {%4,%5,%6,%7}, {%8,%9}, {%0,%1,%2,%3};"
        : "+f"(c[0]), "+f"(c[1]), "+f"(c[2]), "+f"(c[3])
        : "r"(a[0]), "r"(a[1]), "r"(a[2]), "r"(a[3]), "r"(b0), "r"(b1));
}
__device__ __forceinline__ void ldmx4(uint32_t& r0, uint32_t& r1,
                                      uint32_t& r2, uint32_t& r3, uint32_t addr) {
    asm volatile("ldmatrix.sync.aligned.m8n8.x4.shared.b16 {%0,%1,%2,%3}, [%4];"
                 : "=r"(r0), "=r"(r1), "=r"(r2), "=r"(r3) : "r"(addr));
}

// ================= Kernel 1: projection GEMM =================
// Grid 2048: block = (batch, half) -> 64 rows x 192 cols, K=384.
// 8 warps: wm = wid&1 (32 rows), wn = wid>>1 (48 cols).
__global__ void __launch_bounds__(256, 2)
proj_kernel(const float* __restrict__ x,
            const float* __restrict__ Wk,
            const float* __restrict__ Wq,
            const float* __restrict__ Wv) {
    extern __shared__ uint32_t sm[];
    const uint32_t smu = s2u(sm);
    const int tid  = threadIdx.x;
    const int wid  = tid >> 5;
    const int lane = tid & 31;
    const int g4   = lane >> 2;
    const int t4   = lane & 3;
    const int l15  = lane & 15;
    const int l16w = (lane >> 4) * 4;
    const int wm   = wid & 1;
    const int wn   = wid >> 1;
    const int b    = blockIdx.x >> 1;
    const int hm   = blockIdx.x & 1;
    const float* xb = x + (size_t)b * (kT * kC) + hm * 64 * kC;

    float4 xr[2], wr[6];
    // prefetch chunk 0
#pragma unroll
    for (int r = 0; r < 2; ++r) {
        int idx = tid + 256 * r, t = idx >> 3, f4 = idx & 7;
        xr[r] = *(const float4*)(xb + t * kC + f4 * 4);
    }
#pragma unroll
    for (int r = 0; r < 6; ++r) {
        int idx = tid + 256 * r, n = idx >> 3, f4 = idx & 7;
        const float* Wm = (n < 64) ? (Wk + n * kC)
                          : (n < 128) ? (Wq + (n - 64) * kC)
                                      : (Wv + (n - 128) * kC);
        wr[r] = *(const float4*)(Wm + f4 * 4);
    }
    // store chunk 0 -> buf 0
    {
        uint32_t* bx = sm;
        uint32_t* bw = sm + XBUF_W;
#pragma unroll
        for (int r = 0; r < 2; ++r) {
            int idx = tid + 256 * r, t = idx >> 3, f4 = idx & 7;
            *(uint2*)(bx + t * LDXW + f4 * 2) =
                make_uint2(pkh2(xr[r].x, xr[r].y), pkh2(xr[r].z, xr[r].w));
        }
#pragma unroll
        for (int r = 0; r < 6; ++r) {
            int idx = tid + 256 * r, n = idx >> 3, f4 = idx & 7;
            *(uint2*)(bw + n * LDXW + f4 * 2) =
                make_uint2(pkh2(wr[r].x, wr[r].y), pkh2(wr[r].z, wr[r].w));
        }
    }
    __syncthreads();

    float c[2][6][4];
#pragma unroll
    for (int mt = 0; mt < 2; ++mt)
#pragma unroll
        for (int nt = 0; nt < 6; ++nt)
#pragma unroll
            for (int j = 0; j < 4; ++j) c[mt][nt][j] = 0.f;

    for (int cb = 0; cb < kNCH; ++cb) {
        const int p = cb & 1;
        if (cb + 1 < kNCH) {
            const int cbase = (cb + 1) * kCH;
#pragma unroll
            for (int r = 0; r < 2; ++r) {
                int idx = tid + 256 * r, t = idx >> 3, f4 = idx & 7;
                xr[r] = *(const float4*)(xb + t * kC + cbase + f4 * 4);
            }
#pragma unroll
            for (int r = 0; r < 6; ++r) {
                int idx = tid + 256 * r, n = idx >> 3, f4 = idx & 7;
                const float* Wm = (n < 64) ? (Wk + n * kC)
                                  : (n < 128) ? (Wq + (n - 64) * kC)
                                              : (Wv + (n - 128) * kC);
                wr[r] = *(const float4*)(Wm + cbase + f4 * 4);
            }
        }
        {
            const uint32_t bx = smu + 4u * (uint32_t)(p * BUF_W);
            const uint32_t bw = bx + 4u * (uint32_t)XBUF_W;
#pragma unroll
            for (int kk = 0; kk < 2; ++kk) {
                uint32_t a[2][4];
#pragma unroll
                for (int mt = 0; mt < 2; ++mt)
                    ldmx4(a[mt][0], a[mt][1], a[mt][2], a[mt][3],
                          bx + 4 * ((wm * 32 + mt * 16 + l15) * LDXW + kk * 8 + l16w));
#pragma unroll
                for (int np = 0; np < 3; ++np) {
                    uint32_t r0, r1, r2, r3;
                    ldmx4(r0, r1, r2, r3,
                          bw + 4 * ((wn * 48 + np * 16 + l15) * LDXW + kk * 8 + l16w));
                    mma_f16(c[0][2 * np    ], a[0], r0, r2);
                    mma_f16(c[1][2 * np    ], a[1], r0, r2);
                    mma_f16(c[0][2 * np + 1], a[0], r1, r3);
                    mma_f16(c[1][2 * np + 1], a[1], r1, r3);
                }
            }
        }
        if (cb + 1 < kNCH) {
            uint32_t* bx = sm + (p ^ 1) * BUF_W;
            uint32_t* bw = bx + XBUF_W;
#pragma unroll
            for (int r = 0; r < 2; ++r) {
                int idx = tid + 256 * r, t = idx >> 3, f4 = idx & 7;
                *(uint2*)(bx + t * LDXW + f4 * 2) =
                    make_uint2(pkh2(xr[r].x, xr[r].y), pkh2(xr[r].z, xr[r].w));
            }
#pragma unroll
            for (int r = 0; r < 6; ++r) {
                int idx = tid + 256 * r, n = idx >> 3, f4 = idx & 7;
                *(uint2*)(bw + n * LDXW + f4 * 2) =
                    make_uint2(pkh2(wr[r].x, wr[r].y), pkh2(wr[r].z, wr[r].w));
            }
        }
        __syncthreads();
    }

    // epilogue -> global fp16 scratch
    const size_t bo = (size_t)b * (kT * kHS);
#pragma unroll
    for (int mt = 0; mt < 2; ++mt) {
        int r0 = hm * 64 + wm * 32 + mt * 16 + g4, r1 = r0 + 8;
#pragma unroll
        for (int nt = 0; nt < 6; ++nt) {
            int gc = wn * 48 + nt * 8 + 2 * t4;
            int m = gc >> 6, col = gc & 63;
            if (m < 2) {
                __half* base = (m == 0 ? g_K : g_Q) + bo;
                *(uint32_t*)(base + r0 * kHS + col) = pkh2(c[mt][nt][0], c[mt][nt][1]);
                *(uint32_t*)(base + r1 * kHS + col) = pkh2(c[mt][nt][2], c[mt][nt][3]);
            } else {
                __half* vb = g_Vt + bo;
                vb[(col    ) * kT + r0] = __float2half_rn(c[mt][nt][0]);
                vb[(col + 1) * kT + r0] = __float2half_rn(c[mt][nt][1]);
                vb[(col    ) * kT + r1] = __float2half_rn(c[mt][nt][2]);
                vb[(col + 1) * kT + r1] = __float2half_rn(c[mt][nt][3]);
            }
        }
    }
}

// ================= Kernel 2: flash-style attention =================
// Grid 1024 (one CTA per batch), 256 threads / 8 warps.
// Warp w owns rows [16w, 16w+16): QK^T -> warp-local softmax -> PV, P in regs.
__global__ void __launch_bounds__(256, 2)
attn_kernel(float* __restrict__ out) {
    extern __shared__ uint32_t sm[];
    const uint32_t smu = s2u(sm);
    const int tid  = threadIdx.x;
    const int w    = tid >> 5;
    const int lane = tid & 31;
    const int g4   = lane >> 2;
    const int t4   = lane & 3;
    const int l15  = lane & 15;
    const int l16w = (lane >> 4) * 4;
    const int b    = blockIdx.x;

    // cooperative load of Q, K, Vt (fp16) into smem
    const uint4* gq = (const uint4*)(g_Q  + (size_t)b * (kT * kHS));
    const uint4* gk = (const uint4*)(g_K  + (size_t)b * (kT * kHS));
    const uint4* gv = (const uint4*)(g_Vt + (size_t)b * (kT * kHS));
#pragma unroll
    for (int r = 0; r < 4; ++r) {
        int idx = tid + 256 * r, t = idx >> 3, q = idx & 7;
        *(uint4*)(sm + W2_Q + t * LDH + q * 4) = gq[t * 8 + q];
        *(uint4*)(sm + W2_K + t * LDH + q * 4) = gk[t * 8 + q];
    }
#pragma unroll
    for (int r = 0; r < 4; ++r) {
        int idx = tid + 256 * r, h = idx >> 4, q = idx & 15;
        *(uint4*)(sm + W2_VT + h * LDVT + q * 4) = gv[h * 16 + q];
    }
    __syncthreads();

    // ---- S = Q @ K^T for rows [16w,16w+16), col tiles np <= w ----
    // 16 n-tiles of 8 columns each (cols 0..127): cs[nt] covers cols nt*8..nt*8+7
    float cs[16][4];
#pragma unroll
    for (int nt = 0; nt < 16; ++nt)
#pragma unroll
        for (int j = 0; j < 4; ++j) cs[nt][j] = 0.f;

#pragma unroll
    for (int kk = 0; kk < 4; ++kk) {
        uint32_t a[4];
        ldmx4(a[0], a[1], a[2], a[3],
              smu + 4 * (W2_Q + (w * 16 + l15) * LDH + kk * 8 + l16w));
#pragma unroll
        for (int np = 0; np < 8; ++np)
            if (np <= w) {
                uint32_t r0, r1, r2, r3;
                ldmx4(r0, r1, r2, r3,
                      smu + 4 * (W2_K + (np * 16 + l15) * LDH + kk * 8 + l16w));
                mma_f16(cs[2 * np    ], a, r0, r2);
                mma_f16(cs[2 * np + 1], a, r1, r3);
            }
    }

    // ---- warp-local causal softmax (rows g4+16w and g4+8+16w) ----
    const float scale = 0.05103103630798288f;    // 384^-0.5
#pragma unroll
    for (int h = 0; h < 2; ++h) {
        const int row = w * 16 + g4 + 8 * h;
        float m = -1e30f;
#pragma unroll
        for (int nt = 0; nt < 16; ++nt)
            if (nt < 2 * w + 2)
#pragma unroll
                for (int j = 0; j < 2; ++j) {
                    int col = nt * 8 + 2 * t4 + j;
                    float f = cs[nt][2 * h + j] * scale;
                    if (col > row) f = -1e30f;
                    cs[nt][2 * h + j] = f;
                    m = fmaxf(m, f);
                }
        m = fmaxf(m, __shfl_xor_sync(0xffffffffu, m, 1));
        m = fmaxf(m, __shfl_xor_sync(0xffffffffu, m, 2));
        float s = 0.f;
#pragma unroll
        for (int nt = 0; nt < 16; ++nt)
            if (nt < 2 * w + 2)
#pragma unroll
                for (int j = 0; j < 2; ++j) {
                    float e = __expf(cs[nt][2 * h + j] - m);
                    cs[nt][2 * h + j] = e;
                    s += e;
                }
        s += __shfl_xor_sync(0xffffffffu, s, 1);
        s += __shfl_xor_sync(0xffffffffu, s, 2);
        const float inv = 1.0f / s;
#pragma unroll
        for (int nt = 0; nt < 16; ++nt)
            if (nt < 2 * w + 2)
#pragma unroll
                for (int j = 0; j < 2; ++j) cs[nt][2 * h + j] *= inv;
    }

    // ---- pack P into A-fragments (half2); cs dies here ----
    uint32_t pa[8][4];
#pragma unroll
    for (int kk = 0; kk < 8; ++kk) {
        pa[kk][0] = pkh2(cs[2 * kk    ][0], cs[2 * kk    ][1]);
        pa[kk][1] = pkh2(cs[2 * kk    ][2], cs[2 * kk    ][3]);
        pa[kk][2] = pkh2(cs[2 * kk + 1][0], cs[2 * kk + 1][1]);
        pa[kk][3] = pkh2(cs[2 * kk + 1][2], cs[2 * kk + 1][3]);
    }

    // ---- out = P @ V ----
    float co[8][4];
#pragma unroll
    for (int nt = 0; nt < 8; ++nt)
#pragma unroll
        for (int j = 0; j < 4; ++j) co[nt][j] = 0.f;

#pragma unroll
    for (int kk = 0; kk < 8; ++kk)
        if (kk <= w) {
#pragma unroll
            for (int ht = 0; ht < 4; ++ht) {
                uint32_t r0, r1, r2, r3;
                ldmx4(r0, r1, r2, r3,
                      smu + 4 * (W2_VT + (ht * 16 + l15) * LDVT + kk * 8 + l16w));
                mma_f16(co[2 * ht    ], pa[kk], r0, r2);
                mma_f16(co[2 * ht + 1], pa[kk], r1, r3);
            }
        }

    float* ob = out + (size_t)b * (kT * kHS);
    const int r0 = w * 16 + g4, r1 = r0 + 8;
#pragma unroll
    for (int nt = 0; nt < 8; ++nt) {
        int h0 = nt * 8 + 2 * t4;
        *(float2*)(ob + r0 * kHS + h0) = make_float2(co[nt][0], co[nt][1]);
        *(float2*)(ob + r1 * kHS + h0) = make_float2(co[nt][2], co[nt][3]);
    }
}

extern "C" void kernel_launch(void* const* d_in, const int* in_sizes, int n_in,
                              void* d_out, int out_size) {
    const float* x  = (const float*)d_in[0];
    const float* Wk = (const float*)d_in[1];
    const float* Wq = (const float*)d_in[2];
    const float* Wv = (const float*)d_in[3];
    float* out = (float*)d_out;

    const int B = in_sizes[0] / (kT * kC);   // 1024
    cudaFuncSetAttribute(proj_kernel,
                         cudaFuncAttributeMaxDynamicSharedMemorySize, SMEM1_BYTES);
    cudaFuncSetAttribute(attn_kernel,
                         cudaFuncAttributeMaxDynamicSharedMemorySize, SMEM2_BYTES);
    proj_kernel<<<2 * B, 256, SMEM1_BYTES>>>(x, Wk, Wq, Wv);
    attn_kernel<<<B, 256, SMEM2_BYTES>>>(out);
}

// round 11
// speedup vs baseline: 1.0319x; 1.0158x over previous
#include <cuda_runtime.h>
#include <cuda_fp16.h>
#include <cstdint>

// Causal self-attention head as THREE kernels:
//  0) w_prep: convert [Wk|Wq|Wv] fp32 -> fp16 in chunked staging layout (once)
//  1) proj_kernel: KQV projection GEMM (fp16 mma, occ 2), writes fp16 scratch
//  2) attn_kernel: flash-style attention per batch (warp-local softmax)
// B=1024, T=128, C=384, HS=64, fp32 in/out.

static constexpr int kT  = 128;
static constexpr int kC  = 384;
static constexpr int kHS = 64;
static constexpr int kCH = 32;              // K-chunk (floats)
static constexpr int kNCH = kC / kCH;       // 12
static constexpr int kNW  = 192;            // 3*64 combined output cols

// fp16 scratch: K,Q [b][t][h]; Vt [b][h][t]
__device__ __half g_K [1024 * 128 * 64];
__device__ __half g_Q [1024 * 128 * 64];
__device__ __half g_Vt[1024 * 64 * 128];
// fp16 W in chunk-major staging layout: [chunk][n][c]  (n=0..191, c=0..31)
__device__ __half g_Wh[kNCH * kNW * kCH];

// ---- proj_kernel smem (words) ----
static constexpr int LDXW   = 20;                    // 16 half2 data + 4 pad
static constexpr int XBUF_W = 64  * LDXW;            // 1280
static constexpr int WBUF_W = kNW * LDXW;            // 3840
static constexpr int BUF_W  = XBUF_W + WBUF_W;       // 5120
static constexpr int SMEM1_BYTES = 2 * BUF_W * 4;    // 40960

// ---- attn_kernel smem (words) ----
static constexpr int LDH  = 36;                      // Q/K rows: 32 half2 + 4 pad
static constexpr int LDVT = 68;                      // Vt rows: 64 half2 + 4 pad
static constexpr int W2_Q  = 0;
static constexpr int W2_K  = W2_Q + kT * LDH;        // 4608
static constexpr int W2_VT = W2_K + kT * LDH;        // 9216
static constexpr int SMEM2_BYTES = (W2_VT + kHS * LDVT) * 4;   // 54272

// ---------------- helpers ----------------
__device__ __forceinline__ uint32_t pkh2(float a, float b) {
    __half2 h = __floats2half2_rn(a, b);
    return *(uint32_t*)&h;
}
__device__ __forceinline__ uint32_t s2u(const void* p) {
    uint32_t a;
    asm("{ .reg .u64 t; cvta.to.shared.u64 t, %1; cvt.u32.u64 %0, t; }" : "=r"(a) : "l"(p));
    return a;
}
__device__ __forceinline__ void mma_f16(float c[4], const uint32_t a[4],
                                        uint32_t b0, uint32_t b1) {
    asm volatile(
        "mma.sync.aligned.m16n8k16.row.col.f32.f16.f16.f32 "
        "{%0,%1,%2,%3}, {%4,%5,%6,%7}, {%8,%9}, {%0,%1,%2,%3};"
        : "+f"(c[0]), "+f"(c[1]), "+f"(c[2]), "+f"(c[3])
        : "r"(a[0]), "r"(a[1]), "r"(a[2]), "r"(a[3]), "r"(b0), "r"(b1));
}
__device__ __forceinline__ void ldmx4(uint32_t& r0, uint32_t& r1,
                                      uint32_t& r2, uint32_t& r3, uint32_t addr) {
    asm volatile("ldmatrix.sync.aligned.m8n8.x4.shared.b16 {%0,%1,%2,%3}, [%4];"
                 : "=r"(r0), "=r"(r1), "=r"(r2), "=r"(r3) : "r"(addr));
}

// ================= Kernel 0: W fp32 -> fp16 chunk-major =================
// grid 72 x 256 threads, each thread converts 4 consecutive floats of one W row.
__global__ void __launch_bounds__(256)
w_prep(const float* __restrict__ Wk,
       const float* __restrict__ Wq,
       const float* __restrict__ Wv) {
    const int g = (blockIdx.x * 256 + threadIdx.x) * 4;   // 0..73724
    const int n = g / kC;
    const int c = g % kC;
    const float* Wm = (n < 64) ? (Wk + n * kC)
                      : (n < 128) ? (Wq + (n - 64) * kC)
                                  : (Wv + (n - 128) * kC);
    float4 v = *(const float4*)(Wm + c);
    const int cb = c / kCH, cc = c % kCH;
    uint32_t* dst = (uint32_t*)(g_Wh + (cb * kNW + n) * kCH + cc);
    dst[0] = pkh2(v.x, v.y);
    dst[1] = pkh2(v.z, v.w);
}

// ================= Kernel 1: projection GEMM =================
// Grid 2048: block = (batch, half) -> 64 rows x 192 cols, K=384.
// 8 warps: wm = wid&1 (32 rows), wn = wid>>1 (48 cols).
__global__ void __launch_bounds__(256, 2)
proj_kernel(const float* __restrict__ x) {
    extern __shared__ uint32_t sm[];
    const uint32_t smu = s2u(sm);
    const int tid  = threadIdx.x;
    const int wid  = tid >> 5;
    const int lane = tid & 31;
    const int g4   = lane >> 2;
    const int t4   = lane & 3;
    const int l15  = lane & 15;
    const int l16w = (lane >> 4) * 4;
    const int wm   = wid & 1;
    const int wn   = wid >> 1;
    const int b    = blockIdx.x >> 1;
    const int hm   = blockIdx.x & 1;
    const float* xb = x + (size_t)b * (kT * kC) + hm * 64 * kC;

    float4 xr[2];
    uint4  wr[3];
    // prefetch chunk 0
#pragma unroll
    for (int r = 0; r < 2; ++r) {
        int idx = tid + 256 * r, t = idx >> 3, f4 = idx & 7;
        xr[r] = *(const float4*)(xb + t * kC + f4 * 4);
    }
#pragma unroll
    for (int r = 0; r < 3; ++r) {
        int idx = tid + 256 * r;            // 0..767 -> n = idx>>2, q = idx&3
        wr[r] = *(const uint4*)(g_Wh + ((idx >> 2)) * kCH + (idx & 3) * 8);
    }
    // store chunk 0 -> buf 0
    {
        uint32_t* bx = sm;
        uint32_t* bw = sm + XBUF_W;
#pragma unroll
        for (int r = 0; r < 2; ++r) {
            int idx = tid + 256 * r, t = idx >> 3, f4 = idx & 7;
            *(uint2*)(bx + t * LDXW + f4 * 2) =
                make_uint2(pkh2(xr[r].x, xr[r].y), pkh2(xr[r].z, xr[r].w));
        }
#pragma unroll
        for (int r = 0; r < 3; ++r) {
            int idx = tid + 256 * r;
            *(uint4*)(bw + (idx >> 2) * LDXW + (idx & 3) * 4) = wr[r];
        }
    }
    __syncthreads();

    float c[2][6][4];
#pragma unroll
    for (int mt = 0; mt < 2; ++mt)
#pragma unroll
        for (int nt = 0; nt < 6; ++nt)
#pragma unroll
            for (int j = 0; j < 4; ++j) c[mt][nt][j] = 0.f;

    for (int cb = 0; cb < kNCH; ++cb) {
        const int p = cb & 1;
        if (cb + 1 < kNCH) {
            const int cbase = (cb + 1) * kCH;
#pragma unroll
            for (int r = 0; r < 2; ++r) {
                int idx = tid + 256 * r, t = idx >> 3, f4 = idx & 7;
                xr[r] = *(const float4*)(xb + t * kC + cbase + f4 * 4);
            }
            const __half* wsrc = g_Wh + (cb + 1) * (kNW * kCH);
#pragma unroll
            for (int r = 0; r < 3; ++r) {
                int idx = tid + 256 * r;
                wr[r] = *(const uint4*)(wsrc + (idx >> 2) * kCH + (idx & 3) * 8);
            }
        }
        {
            const uint32_t bx = smu + 4u * (uint32_t)(p * BUF_W);
            const uint32_t bw = bx + 4u * (uint32_t)XBUF_W;
#pragma unroll
            for (int kk = 0; kk < 2; ++kk) {
                uint32_t a[2][4];
#pragma unroll
                for (int mt = 0; mt < 2; ++mt)
                    ldmx4(a[mt][0], a[mt][1], a[mt][2], a[mt][3],
                          bx + 4 * ((wm * 32 + mt * 16 + l15) * LDXW + kk * 8 + l16w));
#pragma unroll
                for (int np = 0; np < 3; ++np) {
                    uint32_t r0, r1, r2, r3;
                    ldmx4(r0, r1, r2, r3,
                          bw + 4 * ((wn * 48 + np * 16 + l15) * LDXW + kk * 8 + l16w));
                    mma_f16(c[0][2 * np    ], a[0], r0, r2);
                    mma_f16(c[1][2 * np    ], a[1], r0, r2);
                    mma_f16(c[0][2 * np + 1], a[0], r1, r3);
                    mma_f16(c[1][2 * np + 1], a[1], r1, r3);
                }
            }
        }
        if (cb + 1 < kNCH) {
            uint32_t* bx = sm + (p ^ 1) * BUF_W;
            uint32_t* bw = bx + XBUF_W;
#pragma unroll
            for (int r = 0; r < 2; ++r) {
                int idx = tid + 256 * r, t = idx >> 3, f4 = idx & 7;
                *(uint2*)(bx + t * LDXW + f4 * 2) =
                    make_uint2(pkh2(xr[r].x, xr[r].y), pkh2(xr[r].z, xr[r].w));
            }
#pragma unroll
            for (int r = 0; r < 3; ++r) {
                int idx = tid + 256 * r;
                *(uint4*)(bw + (idx >> 2) * LDXW + (idx & 3) * 4) = wr[r];
            }
        }
        __syncthreads();
    }

    // epilogue -> global fp16 scratch
    const size_t bo = (size_t)b * (kT * kHS);
#pragma unroll
    for (int mt = 0; mt < 2; ++mt) {
        int r0 = hm * 64 + wm * 32 + mt * 16 + g4, r1 = r0 + 8;
#pragma unroll
        for (int nt = 0; nt < 6; ++nt) {
            int gc = wn * 48 + nt * 8 + 2 * t4;
            int m = gc >> 6, col = gc & 63;
            if (m < 2) {
                __half* base = (m == 0 ? g_K : g_Q) + bo;
                *(uint32_t*)(base + r0 * kHS + col) = pkh2(c[mt][nt][0], c[mt][nt][1]);
                *(uint32_t*)(base + r1 * kHS + col) = pkh2(c[mt][nt][2], c[mt][nt][3]);
            } else {
                __half* vb = g_Vt + bo;
                vb[(col    ) * kT + r0] = __float2half_rn(c[mt][nt][0]);
                vb[(col + 1) * kT + r0] = __float2half_rn(c[mt][nt][1]);
                vb[(col    ) * kT + r1] = __float2half_rn(c[mt][nt][2]);
                vb[(col + 1) * kT + r1] = __float2half_rn(c[mt][nt][3]);
            }
        }
    }
}

// ================= Kernel 2: flash-style attention =================
// Grid 1024 (one CTA per batch), 256 threads / 8 warps.
// Warp w owns rows [16w, 16w+16): QK^T -> warp-local softmax -> PV, P in regs.
__global__ void __launch_bounds__(256, 2)
attn_kernel(float* __restrict__ out) {
    extern __shared__ uint32_t sm[];
    const uint32_t smu = s2u(sm);
    const int tid  = threadIdx.x;
    const int w    = tid >> 5;
    const int lane = tid & 31;
    const int g4   = lane >> 2;
    const int t4   = lane & 3;
    const int l15  = lane & 15;
    const int l16w = (lane >> 4) * 4;
    const int b    = blockIdx.x;

    // cooperative load of Q, K, Vt (fp16) into smem
    const uint4* gq = (const uint4*)(g_Q  + (size_t)b * (kT * kHS));
    const uint4* gk = (const uint4*)(g_K  + (size_t)b * (kT * kHS));
    const uint4* gv = (const uint4*)(g_Vt + (size_t)b * (kT * kHS));
#pragma unroll
    for (int r = 0; r < 4; ++r) {
        int idx = tid + 256 * r, t = idx >> 3, q = idx & 7;
        *(uint4*)(sm + W2_Q + t * LDH + q * 4) = gq[t * 8 + q];
        *(uint4*)(sm + W2_K + t * LDH + q * 4) = gk[t * 8 + q];
    }
#pragma unroll
    for (int r = 0; r < 4; ++r) {
        int idx = tid + 256 * r, h = idx >> 4, q = idx & 15;
        *(uint4*)(sm + W2_VT + h * LDVT + q * 4) = gv[h * 16 + q];
    }
    __syncthreads();

    // ---- S = Q @ K^T for rows [16w,16w+16), col tiles np <= w ----
    float cs[16][4];
#pragma unroll
    for (int nt = 0; nt < 16; ++nt)
#pragma unroll
        for (int j = 0; j < 4; ++j) cs[nt][j] = 0.f;

#pragma unroll
    for (int kk = 0; kk < 4; ++kk) {
        uint32_t a[4];
        ldmx4(a[0], a[1], a[2], a[3],
              smu + 4 * (W2_Q + (w * 16 + l15) * LDH + kk * 8 + l16w));
#pragma unroll
        for (int np = 0; np < 8; ++np)
            if (np <= w) {
                uint32_t r0, r1, r2, r3;
                ldmx4(r0, r1, r2, r3,
                      smu + 4 * (W2_K + (np * 16 + l15) * LDH + kk * 8 + l16w));
                mma_f16(cs[2 * np    ], a, r0, r2);
                mma_f16(cs[2 * np + 1], a, r1, r3);
            }
    }

    // ---- warp-local causal softmax (rows g4+16w and g4+8+16w) ----
    const float scale = 0.05103103630798288f;    // 384^-0.5
#pragma unroll
    for (int h = 0; h < 2; ++h) {
        const int row = w * 16 + g4 + 8 * h;
        float m = -1e30f;
#pragma unroll
        for (int nt = 0; nt < 16; ++nt)
            if (nt < 2 * w + 2)
#pragma unroll
                for (int j = 0; j < 2; ++j) {
                    int col = nt * 8 + 2 * t4 + j;
                    float f = cs[nt][2 * h + j] * scale;
                    if (col > row) f = -1e30f;
                    cs[nt][2 * h + j] = f;
                    m = fmaxf(m, f);
                }
        m = fmaxf(m, __shfl_xor_sync(0xffffffffu, m, 1));
        m = fmaxf(m, __shfl_xor_sync(0xffffffffu, m, 2));
        float s = 0.f;
#pragma unroll
        for (int nt = 0; nt < 16; ++nt)
            if (nt < 2 * w + 2)
#pragma unroll
                for (int j = 0; j < 2; ++j) {
                    float e = __expf(cs[nt][2 * h + j] - m);
                    cs[nt][2 * h + j] = e;
                    s += e;
                }
        s += __shfl_xor_sync(0xffffffffu, s, 1);
        s += __shfl_xor_sync(0xffffffffu, s, 2);
        const float inv = 1.0f / s;
#pragma unroll
        for (int nt = 0; nt < 16; ++nt)
            if (nt < 2 * w + 2)
#pragma unroll
                for (int j = 0; j < 2; ++j) cs[nt][2 * h + j] *= inv;
    }

    // ---- pack P into A-fragments (half2); cs dies here ----
    uint32_t pa[8][4];
#pragma unroll
    for (int kk = 0; kk < 8; ++kk) {
        pa[kk][0] = pkh2(cs[2 * kk    ][0], cs[2 * kk    ][1]);
        pa[kk][1] = pkh2(cs[2 * kk    ][2], cs[2 * kk    ][3]);
        pa[kk][2] = pkh2(cs[2 * kk + 1][0], cs[2 * kk + 1][1]);
        pa[kk][3] = pkh2(cs[2 * kk + 1][2], cs[2 * kk + 1][3]);
    }

    // ---- out = P @ V ----
    float co[8][4];
#pragma unroll
    for (int nt = 0; nt < 8; ++nt)
#pragma unroll
        for (int j = 0; j < 4; ++j) co[nt][j] = 0.f;

#pragma unroll
    for (int kk = 0; kk < 8; ++kk)
        if (kk <= w) {
#pragma unroll
            for (int ht = 0; ht < 4; ++ht) {
                uint32_t r0, r1, r2, r3;
                ldmx4(r0, r1, r2, r3,
                      smu + 4 * (W2_VT + (ht * 16 + l15) * LDVT + kk * 8 + l16w));
                mma_f16(co[2 * ht    ], pa[kk], r0, r2);
                mma_f16(co[2 * ht + 1], pa[kk], r1, r3);
            }
        }

    float* ob = out + (size_t)b * (kT * kHS);
    const int r0 = w * 16 + g4, r1 = r0 + 8;
#pragma unroll
    for (int nt = 0; nt < 8; ++nt) {
        int h0 = nt * 8 + 2 * t4;
        *(float2*)(ob + r0 * kHS + h0) = make_float2(co[nt][0], co[nt][1]);
        *(float2*)(ob + r1 * kHS + h0) = make_float2(co[nt][2], co[nt][3]);
    }
}

extern "C" void kernel_launch(void* const* d_in, const int* in_sizes, int n_in,
                              void* d_out, int out_size) {
    const float* x  = (const float*)d_in[0];
    const float* Wk = (const float*)d_in[1];
    const float* Wq = (const float*)d_in[2];
    const float* Wv = (const float*)d_in[3];
    float* out = (float*)d_out;

    const int B = in_sizes[0] / (kT * kC);   // 1024
    cudaFuncSetAttribute(proj_kernel,
                         cudaFuncAttributeMaxDynamicSharedMemorySize, SMEM1_BYTES);
    cudaFuncSetAttribute(attn_kernel,
                         cudaFuncAttributeMaxDynamicSharedMemorySize, SMEM2_BYTES);
    w_prep<<<72, 256>>>(Wk, Wq, Wv);
    proj_kernel<<<2 * B, 256, SMEM1_BYTES>>>(x);
    attn_kernel<<<B, 256, SMEM2_BYTES>>>(out);
}

// round 16
// speedup vs baseline: 1.1146x; 1.0802x over previous
#include <cuda_runtime.h>
#include <cuda_fp16.h>
#include <cstdint>

// Causal self-attention head as THREE kernels:
//  0) w_prep: [Wk|Wq|Wv] fp32 -> fp16 chunk-major (kCH=64) staging
//  1) proj_kernel: KQV GEMM, kCH=64, dist-2 x prefetch, cp.async W 3-ring, occ 2
//  2) attn_kernel: flash-style attention per batch (warp-local softmax)
// B=1024, T=128, C=384, HS=64, fp32 in/out.

static constexpr int kT  = 128;
static constexpr int kC  = 384;
static constexpr int kHS = 64;
static constexpr int kCH = 64;              // C-chunk (floats)
static constexpr int kNCH = kC / kCH;       // 6
static constexpr int kNW  = 192;            // 3*64 combined output cols

// fp16 scratch: K,Q [b][t][h]; Vt [b][h][t]
__device__ __half g_K [1024 * 128 * 64];
__device__ __half g_Q [1024 * 128 * 64];
__device__ __half g_Vt[1024 * 64 * 128];
// fp16 W chunk-major: [chunk][n][c]  (n=0..191, c=0..63)
__device__ __half g_Wh[kNCH * kNW * kCH];

// ---- proj_kernel smem (words) ----
static constexpr int LDXW   = 36;                    // 32 half2-words data + 4 pad
static constexpr int XBUF_W = 64  * LDXW;            // 2304
static constexpr int WBUF_W = kNW * LDXW;            // 6912
static constexpr int XB0 = 0;
static constexpr int XB1 = XBUF_W;                   // 2304
static constexpr int WB0 = 2 * XBUF_W;               // 4608
static constexpr int SMEM1_WORDS = WB0 + 3 * WBUF_W; // 25344
static constexpr int SMEM1_BYTES = SMEM1_WORDS * 4;  // 101376

// ---- attn_kernel smem (words) ----
static constexpr int LDH  = 36;
static constexpr int LDVT = 68;
static constexpr int W2_Q  = 0;
static constexpr int W2_K  = W2_Q + kT * LDH;        // 4608
static constexpr int W2_VT = W2_K + kT * LDH;        // 9216
static constexpr int SMEM2_BYTES = (W2_VT + kHS * LDVT) * 4;   // 54272

// ---------------- helpers ----------------
__device__ __forceinline__ uint32_t pkh2(float a, float b) {
    __half2 h = __floats2half2_rn(a, b);
    return *(uint32_t*)&h;
}
__device__ __forceinline__ uint32_t s2u(const void* p) {
    uint32_t a;
    asm("{ .reg .u64 t; cvta.to.shared.u64 t, %1; cvt.u32.u64 %0, t; }" : "=r"(a) : "l"(p));
    return a;
}
__device__ __forceinline__ void mma_f16(float c[4], const uint32_t a[4],
                                        uint32_t b0, uint32_t b1) {
    asm volatile(
        "mma.sync.aligned.m16n8k16.row.col.f32.f16.f16.f32 "
        "{%0,%1,%2,%3}, {%4,%5,%6,%7}, {%8,%9}, {%0,%1,%2,%3};"
        : "+f"(c[0]), "+f"(c[1]), "+f"(c[2]), "+f"(c[3])
        : "r"(a[0]), "r"(a[1]), "r"(a[2]), "r"(a[3]), "r"(b0), "r"(b1));
}
__device__ __forceinline__ void ldmx4(uint32_t& r0, uint32_t& r1,
                                      uint32_t& r2, uint32_t& r3, uint32_t addr) {
    asm volatile("ldmatrix.sync.aligned.m8n8.x4.shared.b16 {%0,%1,%2,%3}, [%4];"
                 : "=r"(r0), "=r"(r1), "=r"(r2), "=r"(r3) : "r"(addr));
}
__device__ __forceinline__ void cpa16(uint32_t dst, const void* src) {
    asm volatile("cp.async.cg.shared.global [%0], [%1], 16;" :: "r"(dst), "l"(src) : "memory");
}

// ================= Kernel 0: W fp32 -> fp16 chunk-major =================
__global__ void __launch_bounds__(256)
w_prep(const float* __restrict__ Wk,
       const float* __restrict__ Wq,
       const float* __restrict__ Wv) {
    const int g = (blockIdx.x * 256 + threadIdx.x) * 4;   // 0..73724
    const int n = g / kC;
    const int c = g % kC;
    const float* Wm = (n < 64) ? (Wk + n * kC)
                      : (n < 128) ? (Wq + (n - 64) * kC)
                                  : (Wv + (n - 128) * kC);
    float4 v = *(const float4*)(Wm + c);
    const int cb = c / kCH, cc = c % kCH;
    uint32_t* dst = (uint32_t*)(g_Wh + (cb * kNW + n) * kCH + cc);
    dst[0] = pkh2(v.x, v.y);
    dst[1] = pkh2(v.z, v.w);
}

// ================= Kernel 1: projection GEMM =================
// Grid 2048: block = (batch, half) -> 64 rows x 192 cols, K=384, 6 chunks of 64.
// 8 warps: wm = wid&1 (32 rows), wn = wid>>1 (48 cols).
// x reg double-buffer: at iter cb, STORE chunk cb+1 from set (cb&1)^1,
// LOAD chunk cb+2 into set (cb&1). (Set indices verified by full trace.)
__global__ void __launch_bounds__(256, 2)
proj_kernel(const float* __restrict__ x) {
    extern __shared__ uint32_t sm[];
    const uint32_t smu = s2u(sm);
    const int tid  = threadIdx.x;
    const int wid  = tid >> 5;
    const int lane = tid & 31;
    const int g4   = lane >> 2;
    const int t4   = lane & 3;
    const int l15  = lane & 15;
    const int l16w = (lane >> 4) * 4;
    const int wm   = wid & 1;
    const int wn   = wid >> 1;
    const int b    = blockIdx.x >> 1;
    const int hm   = blockIdx.x & 1;
    const float* xb = x + (size_t)b * (kT * kC) + hm * 64 * kC;

    const int xt[4] = { (tid + 0) >> 4, (tid + 256) >> 4, (tid + 512) >> 4, (tid + 768) >> 4 };
    const int xf = tid & 15;
    float4 xr[2][4];    // two prefetch sets

    // ---- prologue ----
#pragma unroll
    for (int r = 0; r < 4; ++r)
        xr[1][r] = *(const float4*)(xb + xt[r] * kC + 0 * kCH + xf * 4);   // chunk 0
    // store chunk 0 -> xbuf0
#pragma unroll
    for (int r = 0; r < 4; ++r)
        *(uint2*)(sm + XB0 + xt[r] * LDXW + xf * 2) =
            make_uint2(pkh2(xr[1][r].x, xr[1][r].y), pkh2(xr[1][r].z, xr[1][r].w));
    // load chunk 1 -> set 1 (chunk0 already stored)
#pragma unroll
    for (int r = 0; r < 4; ++r)
        xr[1][r] = *(const float4*)(xb + xt[r] * kC + 1 * kCH + xf * 4);
    // cp.async W chunk 0 -> wbuf0, chunk 1 -> wbuf1
#pragma unroll
    for (int r = 0; r < 6; ++r) {
        int idx = tid + 256 * r, n = idx >> 3, q = idx & 7;
        cpa16(smu + 4u * (uint32_t)(WB0 + n * LDXW + q * 4),
              g_Wh + (0 * kNW + n) * kCH + q * 8);
    }
    asm volatile("cp.async.commit_group;" ::: "memory");
#pragma unroll
    for (int r = 0; r < 6; ++r) {
        int idx = tid + 256 * r, n = idx >> 3, q = idx & 7;
        cpa16(smu + 4u * (uint32_t)(WB0 + WBUF_W + n * LDXW + q * 4),
              g_Wh + (1 * kNW + n) * kCH + q * 8);
    }
    asm volatile("cp.async.commit_group;" ::: "memory");
    asm volatile("cp.async.wait_group 1;" ::: "memory");   // W0 landed
    __syncthreads();

    float c[2][6][4];
#pragma unroll
    for (int mt = 0; mt < 2; ++mt)
#pragma unroll
        for (int nt = 0; nt < 6; ++nt)
#pragma unroll
            for (int j = 0; j < 4; ++j) c[mt][nt][j] = 0.f;

    for (int cb = 0; cb < kNCH; ++cb) {
        const int p = cb & 1;
        // store x chunk cb+1 (held in set p^1) -> xbuf[p^1]
        if (cb <= 4) {
            const int s = p ^ 1;
            uint32_t* bx = sm + (p ? XB0 : XB1);
#pragma unroll
            for (int r = 0; r < 4; ++r)
                *(uint2*)(bx + xt[r] * LDXW + xf * 2) =
                    make_uint2(pkh2(xr[s][r].x, xr[s][r].y), pkh2(xr[s][r].z, xr[s][r].w));
        }
        // issue x LDG for chunk cb+2 into set p (read last iter; now free)
        if (cb <= 3) {
            const int s = p;                         // <-- FIX (was p^1)
            const int cbase = (cb + 2) * kCH;
#pragma unroll
            for (int r = 0; r < 4; ++r)
                xr[s][r] = *(const float4*)(xb + xt[r] * kC + cbase + xf * 4);
        }
        // issue cp.async W for chunk cb+2
        if (cb <= 3) {
            const __half* wsrc = g_Wh + (cb + 2) * (kNW * kCH);
            const uint32_t wdst = smu + 4u * (uint32_t)(WB0 + ((cb + 2) % 3) * WBUF_W);
#pragma unroll
            for (int r = 0; r < 6; ++r) {
                int idx = tid + 256 * r, n = idx >> 3, q = idx & 7;
                cpa16(wdst + 4u * (uint32_t)(n * LDXW + q * 4), wsrc + n * kCH + q * 8);
            }
            asm volatile("cp.async.commit_group;" ::: "memory");
        }

        // compute chunk cb from xbuf[p], wbuf[cb%3]
        {
            const uint32_t bx = smu + 4u * (uint32_t)(p ? XB1 : XB0);
            const uint32_t bw = smu + 4u * (uint32_t)(WB0 + (cb % 3) * WBUF_W);
#pragma unroll
            for (int kk = 0; kk < 4; ++kk) {
                uint32_t a[2][4];
#pragma unroll
                for (int mt = 0; mt < 2; ++mt)
                    ldmx4(a[mt][0], a[mt][1], a[mt][2], a[mt][3],
                          bx + 4 * ((wm * 32 + mt * 16 + l15) * LDXW + kk * 8 + l16w));
#pragma unroll
                for (int np = 0; np < 3; ++np) {
                    uint32_t r0, r1, r2, r3;
                    ldmx4(r0, r1, r2, r3,
                          bw + 4 * ((wn * 48 + np * 16 + l15) * LDXW + kk * 8 + l16w));
                    mma_f16(c[0][2 * np    ], a[0], r0, r2);
                    mma_f16(c[1][2 * np    ], a[1], r0, r2);
                    mma_f16(c[0][2 * np + 1], a[0], r1, r3);
                    mma_f16(c[1][2 * np + 1], a[1], r1, r3);
                }
            }
        }

        // ensure W chunk cb+1 landed before next iteration
        if (cb <= 3) {
            asm volatile("cp.async.wait_group 1;" ::: "memory");
        } else if (cb == 4) {
            asm volatile("cp.async.wait_group 0;" ::: "memory");
        }
        __syncthreads();
    }

    // epilogue -> global fp16 scratch
    const size_t bo = (size_t)b * (kT * kHS);
#pragma unroll
    for (int mt = 0; mt < 2; ++mt) {
        int r0 = hm * 64 + wm * 32 + mt * 16 + g4, r1 = r0 + 8;
#pragma unroll
        for (int nt = 0; nt < 6; ++nt) {
            int gc = wn * 48 + nt * 8 + 2 * t4;
            int m = gc >> 6, col = gc & 63;
            if (m < 2) {
                __half* base = (m == 0 ? g_K : g_Q) + bo;
                *(uint32_t*)(base + r0 * kHS + col) = pkh2(c[mt][nt][0], c[mt][nt][1]);
                *(uint32_t*)(base + r1 * kHS + col) = pkh2(c[mt][nt][2], c[mt][nt][3]);
            } else {
                __half* vb = g_Vt + bo;
                vb[(col    ) * kT + r0] = __float2half_rn(c[mt][nt][0]);
                vb[(col + 1) * kT + r0] = __float2half_rn(c[mt][nt][1]);
                vb[(col    ) * kT + r1] = __float2half_rn(c[mt][nt][2]);
                vb[(col + 1) * kT + r1] = __float2half_rn(c[mt][nt][3]);
            }
        }
    }
}

// ================= Kernel 2: flash-style attention =================
__global__ void __launch_bounds__(256, 2)
attn_kernel(float* __restrict__ out) {
    extern __shared__ uint32_t sm[];
    const uint32_t smu = s2u(sm);
    const int tid  = threadIdx.x;
    const int w    = tid >> 5;
    const int lane = tid & 31;
    const int g4   = lane >> 2;
    const int t4   = lane & 3;
    const int l15  = lane & 15;
    const int l16w = (lane >> 4) * 4;
    const int b    = blockIdx.x;

    const uint4* gq = (const uint4*)(g_Q  + (size_t)b * (kT * kHS));
    const uint4* gk = (const uint4*)(g_K  + (size_t)b * (kT * kHS));
    const uint4* gv = (const uint4*)(g_Vt + (size_t)b * (kT * kHS));
#pragma unroll
    for (int r = 0; r < 4; ++r) {
        int idx = tid + 256 * r, t = idx >> 3, q = idx & 7;
        *(uint4*)(sm + W2_Q + t * LDH + q * 4) = gq[t * 8 + q];
        *(uint4*)(sm + W2_K + t * LDH + q * 4) = gk[t * 8 + q];
    }
#pragma unroll
    for (int r = 0; r < 4; ++r) {
        int idx = tid + 256 * r, h = idx >> 4, q = idx & 15;
        *(uint4*)(sm + W2_VT + h * LDVT + q * 4) = gv[h * 16 + q];
    }
    __syncthreads();

    float cs[16][4];
#pragma unroll
    for (int nt = 0; nt < 16; ++nt)
#pragma unroll
        for (int j = 0; j < 4; ++j) cs[nt][j] = 0.f;

#pragma unroll
    for (int kk = 0; kk < 4; ++kk) {
        uint32_t a[4];
        ldmx4(a[0], a[1], a[2], a[3],
              smu + 4 * (W2_Q + (w * 16 + l15) * LDH + kk * 8 + l16w));
#pragma unroll
        for (int np = 0; np < 8; ++np)
            if (np <= w) {
                uint32_t r0, r1, r2, r3;
                ldmx4(r0, r1, r2, r3,
                      smu + 4 * (W2_K + (np * 16 + l15) * LDH + kk * 8 + l16w));
                mma_f16(cs[2 * np    ], a, r0, r2);
                mma_f16(cs[2 * np + 1], a, r1, r3);
            }
    }

    const float scale = 0.05103103630798288f;    // 384^-0.5
#pragma unroll
    for (int h = 0; h < 2; ++h) {
        const int row = w * 16 + g4 + 8 * h;
        float m = -1e30f;
#pragma unroll
        for (int nt = 0; nt < 16; ++nt)
            if (nt < 2 * w + 2)
#pragma unroll
                for (int j = 0; j < 2; ++j) {
                    int col = nt * 8 + 2 * t4 + j;
                    float f = cs[nt][2 * h + j] * scale;
                    if (col > row) f = -1e30f;
                    cs[nt][2 * h + j] = f;
                    m = fmaxf(m, f);
                }
        m = fmaxf(m, __shfl_xor_sync(0xffffffffu, m, 1));
        m = fmaxf(m, __shfl_xor_sync(0xffffffffu, m, 2));
        float s = 0.f;
#pragma unroll
        for (int nt = 0; nt < 16; ++nt)
            if (nt < 2 * w + 2)
#pragma unroll
                for (int j = 0; j < 2; ++j) {
                    float e = __expf(cs[nt][2 * h + j] - m);
                    cs[nt][2 * h + j] = e;
                    s += e;
                }
        s += __shfl_xor_sync(0xffffffffu, s, 1);
        s += __shfl_xor_sync(0xffffffffu, s, 2);
        const float inv = 1.0f / s;
#pragma unroll
        for (int nt = 0; nt < 16; ++nt)
            if (nt < 2 * w + 2)
#pragma unroll
                for (int j = 0; j < 2; ++j) cs[nt][2 * h + j] *= inv;
    }

    uint32_t pa[8][4];
#pragma unroll
    for (int kk = 0; kk < 8; ++kk) {
        pa[kk][0] = pkh2(cs[2 * kk    ][0], cs[2 * kk    ][1]);
        pa[kk][1] = pkh2(cs[2 * kk    ][2], cs[2 * kk    ][3]);
        pa[kk][2] = pkh2(cs[2 * kk + 1][0], cs[2 * kk + 1][1]);
        pa[kk][3] = pkh2(cs[2 * kk + 1][2], cs[2 * kk + 1][3]);
    }

    float co[8][4];
#pragma unroll
    for (int nt = 0; nt < 8; ++nt)
#pragma unroll
        for (int j = 0; j < 4; ++j) co[nt][j] = 0.f;

#pragma unroll
    for (int kk = 0; kk < 8; ++kk)
        if (kk <= w) {
#pragma unroll
            for (int ht = 0; ht < 4; ++ht) {
                uint32_t r0, r1, r2, r3;
                ldmx4(r0, r1, r2, r3,
                      smu + 4 * (W2_VT + (ht * 16 + l15) * LDVT + kk * 8 + l16w));
                mma_f16(co[2 * ht    ], pa[kk], r0, r2);
                mma_f16(co[2 * ht + 1], pa[kk], r1, r3);
            }
        }

    float* ob = out + (size_t)b * (kT * kHS);
    const int r0 = w * 16 + g4, r1 = r0 + 8;
#pragma unroll
    for (int nt = 0; nt < 8; ++nt) {
        int h0 = nt * 8 + 2 * t4;
        *(float2*)(ob + r0 * kHS + h0) = make_float2(co[nt][0], co[nt][1]);
        *(float2*)(ob + r1 * kHS + h0) = make_float2(co[nt][2], co[nt][3]);
    }
}

extern "C" void kernel_launch(void* const* d_in, const int* in_sizes, int n_in,
                              void* d_out, int out_size) {
    const float* x  = (const float*)d_in[0];
    const float* Wk = (const float*)d_in[1];
    const float* Wq = (const float*)d_in[2];
    const float* Wv = (const float*)d_in[3];
    float* out = (float*)d_out;

    const int B = in_sizes[0] / (kT * kC);   // 1024
    cudaFuncSetAttribute(proj_kernel,
                         cudaFuncAttributeMaxDynamicSharedMemorySize, SMEM1_BYTES);
    cudaFuncSetAttribute(attn_kernel,
                         cudaFuncAttributeMaxDynamicSharedMemorySize, SMEM2_BYTES);
    w_prep<<<72, 256>>>(Wk, Wq, Wv);
    proj_kernel<<<2 * B, 256, SMEM1_BYTES>>>(x);
    attn_kernel<<<B, 256, SMEM2_BYTES>>>(out);
}